// round 15
// baseline (speedup 1.0000x reference)
#include <cuda_runtime.h>
#include <cuda_bf16.h>
#include <cuda_fp16.h>
#include <mma.h>
#include <math.h>

using namespace nvcuda;

// ---------------- problem constants ----------------
#define Bq   4
#define Cc   128
#define Hh   64
#define Ww   64
#define Ll   4096          // H*W
#define Gg   4
#define DIi  64
#define DSs  16
#define NCk  64            // number of scan chunks
#define CTk  64            // chunk length  (NCk*CTk == Ll)

typedef unsigned long long ull;

// ---------------- f32x2 helpers ----------------
__device__ __forceinline__ ull pk2(float a, float b) {
    ull r; asm("mov.b64 %0,{%1,%2};" : "=l"(r) : "f"(a), "f"(b)); return r;
}
__device__ __forceinline__ void upk2(ull v, float& a, float& b) {
    asm("mov.b64 {%0,%1},%2;" : "=f"(a), "=f"(b) : "l"(v));
}
__device__ __forceinline__ ull f2fma(ull a, ull b, ull c) {
    ull r; asm("fma.rn.f32x2 %0,%1,%2,%3;" : "=l"(r) : "l"(a), "l"(b), "l"(c)); return r;
}
__device__ __forceinline__ ull f2mul(ull a, ull b) {
    ull r; asm("mul.rn.f32x2 %0,%1,%2;" : "=l"(r) : "l"(a), "l"(b)); return r;
}

// ---------------- scratch ----------------
__device__ float g_xs[Bq * Ll * Cc];
__device__ float g_xn[Bq * Ll * Cc];
__device__ __align__(16) __half g_u2[Gg * Bq * Ll * DIi];     // u fp16
__device__ __align__(16) __half g_z2[Gg * Bq * Ll * DIi];     // z fp16
__device__ __half2 g_du2[Gg * 2 * Bq * Ll * DIi];             // (dt, uc) fp16 pair
__device__ __half2 g_Bm2[Gg * 2 * Bq * Ll * 8];               // B fp16, pairs
__device__ __half2 g_Cm2[Gg * 2 * Bq * Ll * 8];               // C fp16, pairs
__device__ __align__(16) __half g_y2[Gg * 2 * Bq * Ll * DIi]; // y fp16
__device__ float g_xm[Bq * Ll * Cc];
__device__ float g_cq[32 * NCk * DIi];                        // scalar chunk decay q
__device__ __align__(16) float g_carryQ[32 * NCk * DIi * DSs];
__device__ __align__(16) float g_hstart[32 * NCk * DIi * DSs];
__device__ int g_fastflag;

// ---------------- kernel 0: S4D structure check (hoisted) ----------------
__global__ void k_checkA(const float* __restrict__ A_log) {
    int ok = 1;
    for (int i = threadIdx.x; i < Gg * 2 * DIi * DSs; i += 128) {
        int s = i & 15;
        float Av = __expf(A_log[i]);
        if (fabsf(Av - (float)(s + 1)) > 1e-3f * (float)(s + 1)) ok = 0;
    }
    ok = __syncthreads_and(ok);
    if (threadIdx.x == 0) g_fastflag = ok;
}

// ---------------- kernel 1: conv-pos-enc + pos_embed + LayerNorm ----------------
__global__ void k_posln(const float* __restrict__ x, const float* __restrict__ pcw,
                        const float* __restrict__ pcb, const float* __restrict__ lng,
                        const float* __restrict__ lnb, const float* __restrict__ pe) {
    __shared__ float sv[64 * 129];
    __shared__ float sw[128 * 9];
    __shared__ float smu[64], srs[64];
    int b = blockIdx.x >> 6;
    int h = blockIdx.x & 63;
    int tid = threadIdx.x;
    for (int i = tid; i < 128 * 9; i += 256) sw[i] = pcw[i];
    __syncthreads();
    for (int idx = tid; idx < 8192; idx += 256) {
        int c = idx >> 6, w = idx & 63;
        const float* xb = x + ((size_t)(b * Cc + c)) * (Hh * Ww);
        float acc = 0.f;
#pragma unroll
        for (int kh = 0; kh < 3; kh++) {
            int hh = h + kh - 1;
            if (hh < 0 || hh >= Hh) continue;
#pragma unroll
            for (int kw = 0; kw < 3; kw++) {
                int w2 = w + kw - 1;
                if (w2 < 0 || w2 >= Ww) continue;
                acc += xb[hh * Ww + w2] * sw[c * 9 + kh * 3 + kw];
            }
        }
        sv[w * 129 + c] = xb[h * Ww + w] + acc + pcb[c];
    }
    __syncthreads();
    for (int idx = tid; idx < 8192; idx += 256) {
        int l = idx >> 7, c = idx & 127;
        sv[l * 129 + c] += pe[((size_t)(h * 64 + l)) * 128 + c];
    }
    __syncthreads();
    if (tid < 64) {
        float s = 0.f, s2 = 0.f;
        for (int c = 0; c < 128; c++) { float v = sv[tid * 129 + c]; s += v; s2 += v * v; }
        float mu = s * (1.f / 128.f);
        float var = s2 * (1.f / 128.f) - mu * mu;
        smu[tid] = mu;
        srs[tid] = rsqrtf(var + 1e-5f);
    }
    __syncthreads();
    size_t base = ((size_t)b * Ll + h * Ww) * Cc;
    for (int idx = tid; idx < 8192; idx += 256) {
        int l = idx >> 7, c = idx & 127;
        float v = sv[l * 129 + c];
        g_xs[base + idx] = v;
        g_xn[base + idx] = (v - smu[l]) * srs[l] * lng[c] + lnb[c];
    }
}

// ---------------- kernel 2: per-group in-projection; u,z stored fp16 ----------------
__global__ void k_win(const float* __restrict__ Win) {
    int g = blockIdx.x >> 8;
    int tile = blockIdx.x & 255;
    int row0 = tile * 64;
    int tid = threadIdx.x;
    __shared__ float sX[32 * 68];   // [k][r]
    __shared__ float sW[32 * 132];  // [k][o]
    for (int i = tid; i < 2048; i += 256) {
        int r = i >> 5, k = i & 31;
        sX[k * 68 + r] = g_xn[(size_t)(row0 + r) * 128 + g * 32 + k];
    }
    for (int i = tid; i < 4096; i += 256) {
        int o = i >> 5, k = i & 31;
        sW[k * 132 + o] = Win[g * 4096 + i];
    }
    __syncthreads();
    int rg = tid & 15, og = tid >> 4;
    int r0 = rg * 4, o0 = og * 8;
    float acc[4][8];
#pragma unroll
    for (int i = 0; i < 4; i++)
#pragma unroll
        for (int j = 0; j < 8; j++) acc[i][j] = 0.f;
#pragma unroll 4
    for (int k = 0; k < 32; k++) {
        float4 xv = *(const float4*)&sX[k * 68 + r0];
        float4 wa = *(const float4*)&sW[k * 132 + o0];
        float4 wb = *(const float4*)&sW[k * 132 + o0 + 4];
        float xr[4] = {xv.x, xv.y, xv.z, xv.w};
        float wv[8] = {wa.x, wa.y, wa.z, wa.w, wb.x, wb.y, wb.z, wb.w};
#pragma unroll
        for (int i = 0; i < 4; i++)
#pragma unroll
            for (int j = 0; j < 8; j++) acc[i][j] += xr[i] * wv[j];
    }
#pragma unroll
    for (int i = 0; i < 4; i++) {
        size_t row = (size_t)(row0 + r0 + i);
        __half2 h0 = __floats2half2_rn(acc[i][0], acc[i][1]);
        __half2 h1 = __floats2half2_rn(acc[i][2], acc[i][3]);
        __half2 h2v = __floats2half2_rn(acc[i][4], acc[i][5]);
        __half2 h3 = __floats2half2_rn(acc[i][6], acc[i][7]);
        if (og < 8) {
            __half2* p = (__half2*)&g_u2[((size_t)g * (Bq * Ll) + row) * 64 + o0];
            p[0] = h0; p[1] = h1; p[2] = h2v; p[3] = h3;
        } else {
            __half2* p = (__half2*)&g_z2[((size_t)g * (Bq * Ll) + row) * 64 + (o0 - 64)];
            p[0] = h0; p[1] = h1; p[2] = h2v; p[3] = h3;
        }
    }
}

// ---------------- kernel 3: causal dwconv + silu + xproj(WMMA) + dt ----------------
__global__ __launch_bounds__(256) void k_convproj(
        const float* __restrict__ conv_w, const float* __restrict__ conv_b,
        const float* __restrict__ xproj_W, const float* __restrict__ dt_W,
        const float* __restrict__ dt_b) {
    __shared__ __align__(32) float su[64 * 73];        // [di][j<73]
    __shared__ __align__(32) __half suc_h[64 * 72];    // [di][tl<72]  == A col-major ld 72
    __half* sxw_h = (__half*)su;                       // [k=di][o<40] row-major ld 40
    float*  sdbl  = su + 1280;                         // [tl][o<48]   ld 48

    int bi = blockIdx.x;            // 2048 blocks
    int tile = bi & 63;
    int b = (bi >> 6) & 3;
    int dir = (bi >> 8) & 1;
    int g = bi >> 9;
    int tid = threadIdx.x;
    int gd = g * 2 + dir;
    int t0 = tile * 64;

    // stage u (fp16 -> fp32) via half2, rows t0-3 .. t0+66
    const __half* ub = g_u2 + ((size_t)g * Bq + b) * Ll * 64;
    for (int i = tid; i < 70 * 32; i += 256) {
        int j = i >> 5;
        int di2 = (i & 31) * 2;
        int t = t0 - 3 + j;
        float lo = 0.f, hi = 0.f;
        if (t >= 0 && t < Ll) {
            float2 v = __half22float2(*(const __half2*)&ub[(size_t)t * 64 + di2]);
            lo = v.x; hi = v.y;
        }
        su[di2 * 73 + j] = lo;
        su[(di2 + 1) * 73 + j] = hi;
    }
    __syncthreads();

    // conv + silu -> suc_h (half), sliding window
    {
        int di = tid & 63;
        int tlg = tid >> 6;
        int tl0 = tlg * 16;
        float w0 = conv_w[gd * 256 + di * 4 + 0];
        float w1 = conv_w[gd * 256 + di * 4 + 1];
        float w2 = conv_w[gd * 256 + di * 4 + 2];
        float w3 = conv_w[gd * 256 + di * 4 + 3];
        float cb = conv_b[gd * 64 + di];
        const float* sud = &su[di * 73];
        if (dir == 0) {
            float x0 = sud[tl0 + 0], x1 = sud[tl0 + 1], x2 = sud[tl0 + 2];
#pragma unroll
            for (int m = 0; m < 16; m++) {
                float x3 = sud[tl0 + m + 3];
                float a = w0 * x0 + w1 * x1 + w2 * x2 + w3 * x3 + cb;
                suc_h[di * 72 + tl0 + m] = __float2half(a / (1.f + __expf(-a)));
                x0 = x1; x1 = x2; x2 = x3;
            }
        } else {
            float x0 = sud[tl0 + 3], x1 = sud[tl0 + 4], x2 = sud[tl0 + 5];
#pragma unroll
            for (int m = 0; m < 16; m++) {
                float x3 = sud[tl0 + m + 6];
                float a = w3 * x0 + w2 * x1 + w1 * x2 + w0 * x3 + cb;
                suc_h[di * 72 + tl0 + m] = __float2half(a / (1.f + __expf(-a)));
                x0 = x1; x1 = x2; x2 = x3;
            }
        }
    }
    __syncthreads();

    // stage xproj weights (half), [k][o] ld 40; zero pads o=34..39
    for (int i = tid; i < 2176; i += 256) {
        int o = i >> 6, di = i & 63;
        sxw_h[di * 40 + o] = __float2half(xproj_W[gd * 2176 + i]);
    }
    for (int i = tid; i < 384; i += 256) {
        int k = i / 6, o = 34 + (i % 6);
        sxw_h[k * 40 + o] = __float2half(0.f);
    }
    __syncthreads();

    // WMMA GEMM: out[tl 64][o 48] = A(suc_h col-major) @ B(sxw_h row-major)
    {
        int warp = tid >> 5;
        for (int t = warp; t < 12; t += 8) {
            int mi = t & 3;
            int ni = t >> 2;
            wmma::fragment<wmma::accumulator, 16, 16, 16, float> cf;
            wmma::fill_fragment(cf, 0.f);
#pragma unroll
            for (int k0 = 0; k0 < 4; k0++) {
                wmma::fragment<wmma::matrix_a, 16, 16, 16, __half, wmma::col_major> af;
                wmma::fragment<wmma::matrix_b, 16, 16, 16, __half, wmma::row_major> bf;
                wmma::load_matrix_sync(af, &suc_h[(k0 * 16) * 72 + mi * 16], 72);
                wmma::load_matrix_sync(bf, &sxw_h[(k0 * 16) * 40 + ni * 16], 40);
                wmma::mma_sync(cf, af, bf, cf);
            }
            wmma::store_matrix_sync(&sdbl[(mi * 16) * 48 + ni * 16], cf, 48, wmma::mem_row_major);
        }
    }
    __syncthreads();

    // dt phase: write packed (dt, uc) fp16 pair
    __half2* dug = g_du2 + ((size_t)gd * Bq + b) * Ll * 64;
    {
        int di = tid & 63;
        int tlg = tid >> 6;
        float dw0 = dt_W[gd * 128 + di * 2 + 0];
        float dw1 = dt_W[gd * 128 + di * 2 + 1];
        float db  = dt_b[gd * 64 + di];
#pragma unroll 4
        for (int m = 0; m < 16; m++) {
            int tl = tlg * 16 + m;
            float r = sdbl[tl * 48 + 0] * dw0 + sdbl[tl * 48 + 1] * dw1 + db;
            float sp = (r > 15.f) ? r : log1pf(__expf(r));
            __half2 v;
            v.x = __float2half(sp);
            v.y = suc_h[di * 72 + tl];
            dug[(size_t)(t0 + tl) * 64 + di] = v;
        }
    }
    __half2* Bmg = g_Bm2 + ((size_t)gd * Bq + b) * Ll * 8;
    __half2* Cmg = g_Cm2 + ((size_t)gd * Bq + b) * Ll * 8;
    for (int i = tid; i < 512; i += 256) {
        int tl = i >> 3, dsp = i & 7;
        Bmg[(size_t)(t0 + tl) * 8 + dsp] =
            __floats2half2_rn(sdbl[tl * 48 + 2 + dsp * 2], sdbl[tl * 48 + 3 + dsp * 2]);
        Cmg[(size_t)(t0 + tl) * 8 + dsp] =
            __floats2half2_rn(sdbl[tl * 48 + 18 + dsp * 2], sdbl[tl * 48 + 19 + dsp * 2]);
    }
}

// ---------------- kernels 4/6: chunked selective scan (fp16 streams, hoisted A-check) ----------------
template <int PASS>
__global__ __launch_bounds__(128, 8) void k_scan(const float* __restrict__ A_log,
                                                 const float* __restrict__ Dskip) {
    __shared__ __align__(16) float sB[2][CTk * 16];
    __shared__ __align__(16) float sC_[2][CTk * 16];
    int tid = threadIdx.x;
    int unit = tid >> 6;
    int di = tid & 63;
    int ug = blockIdx.x * 2 + unit;
    int seq = ug >> 6;
    int c = ug & 63;
    int b = seq & 3;
    int dir = (seq >> 2) & 1;
    int g = seq >> 3;
    int gd = g * 2 + dir;
    size_t base_td = ((size_t)gd * Bq + b) * Ll * 64;
    size_t base_s2 = ((size_t)gd * Bq + b) * Ll * 8;
    size_t base_z  = ((size_t)g * Bq + b) * Ll * 64;
    int sigma0 = c * CTk;
    int tstart = dir ? (Ll - 1 - sigma0) : sigma0;
    int tstep  = dir ? -1 : 1;
    const __half2* Bm2 = g_Bm2 + base_s2;
    const __half2* Cm2 = g_Cm2 + base_s2;
    for (int i = di; i < CTk * 8; i += 64) {
        int sl = i >> 3, dsp = i & 7;
        int t = tstart + tstep * sl;
        *(float2*)&sB[unit][sl * 16 + dsp * 2] = __half22float2(Bm2[(size_t)t * 8 + dsp]);
        if (PASS == 2)
            *(float2*)&sC_[unit][sl * 16 + dsp * 2] = __half22float2(Cm2[(size_t)t * 8 + dsp]);
    }
    int fast = g_fastflag;
    float Dv = (PASS == 2) ? Dskip[gd * 64 + di] : 0.f;
    size_t coff = (((size_t)seq * NCk + c) * 64 + di) * 16;
    __syncthreads();

    int pstep = tstep * 64;
    const __half2* dup = g_du2 + base_td + (size_t)tstart * 64 + di;
    const __half*  zp  = g_z2  + base_z  + (size_t)tstart * 64 + di;
    __half*        yp  = g_y2  + base_td + (size_t)tstart * 64 + di;

    if (fast) {
        ull h2[8];
        if (PASS == 1) {
#pragma unroll
            for (int j = 0; j < 8; j++) h2[j] = 0ull;
        } else {
            const ull* hp = (const ull*)&g_hstart[coff];
#pragma unroll
            for (int j = 0; j < 8; j++) h2[j] = hp[j];
        }
        float sumdt = 0.f;
        float2 cur = __half22float2(__ldg(dup));
        float zcur = (PASS == 2) ? __half2float(__ldg(zp)) : 0.f;
        for (int sl = 0; sl < CTk; sl++) {
            float2 nxt = cur;
            float znxt = zcur;
            if (sl < CTk - 1) {
                dup += pstep;
                nxt = __half22float2(__ldg(dup));
                if (PASS == 2) { zp += pstep; znxt = __half2float(__ldg(zp)); }
            }
            float dtv = cur.x, ucv = cur.y;
            float dtu = dtv * ucv;
            float p = __expf(-dtv);
            float p2 = p * p;
            float p4 = p2 * p2;
            float p8 = p4 * p4;
            ull q2 = pk2(p2, p2);
            ull q4 = pk2(p4, p4);
            ull q8 = pk2(p8, p8);
            ull d0 = pk2(p, p2);
            ull d1 = f2mul(d0, q2);
            ull d2 = f2mul(d0, q4);
            ull d3 = f2mul(d1, q4);
            ull d4 = f2mul(d0, q8);
            ull d5 = f2mul(d1, q8);
            ull d6 = f2mul(d2, q8);
            ull d7 = f2mul(d3, q8);
            ull du2 = pk2(dtu, dtu);
            if (PASS == 1) sumdt += dtv;
            const ull* bp = (const ull*)&sB[unit][sl * 16];
            h2[0] = f2fma(d0, h2[0], f2mul(du2, bp[0]));
            h2[1] = f2fma(d1, h2[1], f2mul(du2, bp[1]));
            h2[2] = f2fma(d2, h2[2], f2mul(du2, bp[2]));
            h2[3] = f2fma(d3, h2[3], f2mul(du2, bp[3]));
            h2[4] = f2fma(d4, h2[4], f2mul(du2, bp[4]));
            h2[5] = f2fma(d5, h2[5], f2mul(du2, bp[5]));
            h2[6] = f2fma(d6, h2[6], f2mul(du2, bp[6]));
            h2[7] = f2fma(d7, h2[7], f2mul(du2, bp[7]));
            if (PASS == 2) {
                const ull* cp = (const ull*)&sC_[unit][sl * 16];
                ull a0 = f2mul(h2[0], cp[0]);
                ull a1 = f2mul(h2[4], cp[4]);
                a0 = f2fma(h2[1], cp[1], a0);
                a1 = f2fma(h2[5], cp[5], a1);
                a0 = f2fma(h2[2], cp[2], a0);
                a1 = f2fma(h2[6], cp[6], a1);
                a0 = f2fma(h2[3], cp[3], a0);
                a1 = f2fma(h2[7], cp[7], a1);
                float x0, x1, x2, x3;
                upk2(a0, x0, x1);
                upk2(a1, x2, x3);
                float y = (x0 + x2) + (x1 + x3) + ucv * Dv;
                y *= zcur / (1.f + __expf(-zcur));
                *yp = __float2half(y);
                yp += pstep;
            }
            cur = nxt;
            zcur = znxt;
        }
        if (PASS == 1) {
            g_cq[((size_t)seq * NCk + c) * 64 + di] = __expf(-sumdt);
            ull* cQ = (ull*)&g_carryQ[coff];
#pragma unroll
            for (int j = 0; j < 8; j++) cQ[j] = h2[j];
        }
    } else {
        float Av[16];
#pragma unroll
        for (int s = 0; s < 16; s++) Av[s] = -__expf(A_log[(gd * 64 + di) * 16 + s]);
        float h[16];
        float sumdt = 0.f;
        if (PASS == 1) {
#pragma unroll
            for (int s = 0; s < 16; s++) h[s] = 0.f;
        } else {
#pragma unroll
            for (int s = 0; s < 16; s++) h[s] = g_hstart[coff + s];
        }
        for (int sl = 0; sl < CTk; sl++) {
            float2 duv = __half22float2(dup[(size_t)(tstep * sl) * 64]);
            float dtv = duv.x, ucv = duv.y;
            float dtu = dtv * ucv;
            float acc = 0.f;
            if (PASS == 1) sumdt += dtv;
#pragma unroll
            for (int s = 0; s < 16; s++) {
                float dA = __expf(dtv * Av[s]);
                h[s] = dA * h[s] + dtu * sB[unit][sl * 16 + s];
                if (PASS == 2) acc += h[s] * sC_[unit][sl * 16 + s];
            }
            if (PASS == 2) {
                float zv = __half2float(zp[(size_t)(tstep * sl) * 64]);
                float y = acc + ucv * Dv;
                y *= zv / (1.f + __expf(-zv));
                yp[(size_t)(tstep * sl) * 64] = __float2half(y);
            }
        }
        if (PASS == 1) {
            g_cq[((size_t)seq * NCk + c) * 64 + di] = __expf(-sumdt);
#pragma unroll
            for (int s = 0; s < 16; s++) g_carryQ[coff + s] = h[s];
        }
    }
}

// ---------------- kernel 5: compose chunk carries (q-power reconstruction) ----------------
__global__ void k_scanfix() {
    int idx = blockIdx.x * 128 + threadIdx.x;
    int seq = idx >> 9;
    int e2 = idx & 511;
    int di = e2 >> 3;
    int j  = e2 & 7;
    ull h = 0ull;
    const ull* Q = (const ull*)g_carryQ;
    ull* H = (ull*)g_hstart;
#pragma unroll 8
    for (int c = 0; c < NCk; c++) {
        size_t off = ((size_t)seq * NCk + c) * 512 + e2;
        float q = g_cq[((size_t)seq * NCk + c) * 64 + di];
        float q2 = q * q;
        float q4 = q2 * q2;
        float q8 = q4 * q4;
        float qp = ((j & 1) ? q2 : 1.f) * ((j & 2) ? q4 : 1.f) * ((j & 4) ? q8 : 1.f);
        ull P = pk2(q * qp, q2 * qp);
        H[off] = h;
        h = f2fma(P, h, Q[off]);
    }
}

// ---------------- kernel 7: (yf+yb) @ Wout^T -> x_mamba, register tiled ----------------
__global__ void k_wout(const float* __restrict__ Wout) {
    int g = blockIdx.x >> 8;
    int tile = blockIdx.x & 255;
    int row0 = tile * 64;
    int tid = threadIdx.x;    // 128 threads
    __shared__ float sY[64 * 68];   // [k][r]
    __shared__ float sW[64 * 36];   // [k][o]
    size_t basef = ((size_t)(g * 2 + 0) * Bq) * Ll * 64;
    size_t baseb = ((size_t)(g * 2 + 1) * Bq) * Ll * 64;
    for (int i = tid; i < 4096; i += 128) {
        int r = i >> 6, k = i & 63;
        size_t ro = (size_t)(row0 + r) * 64 + k;
        sY[k * 68 + r] = __half2float(g_y2[basef + ro]) + __half2float(g_y2[baseb + ro]);
    }
    for (int i = tid; i < 2048; i += 128) {
        int o = i >> 6, k = i & 63;
        sW[k * 36 + o] = Wout[g * 2048 + i];
    }
    __syncthreads();
    int rg = tid & 15, og = tid >> 4;
    int r0 = rg * 4, o0 = og * 4;
    float acc[4][4];
#pragma unroll
    for (int i = 0; i < 4; i++)
#pragma unroll
        for (int j = 0; j < 4; j++) acc[i][j] = 0.f;
#pragma unroll 4
    for (int k = 0; k < 64; k++) {
        float4 yv = *(const float4*)&sY[k * 68 + r0];
        float4 wv = *(const float4*)&sW[k * 36 + o0];
        float yr[4] = {yv.x, yv.y, yv.z, yv.w};
        float wr[4] = {wv.x, wv.y, wv.z, wv.w};
#pragma unroll
        for (int i = 0; i < 4; i++)
#pragma unroll
            for (int j = 0; j < 4; j++) acc[i][j] += yr[i] * wr[j];
    }
#pragma unroll
    for (int i = 0; i < 4; i++) {
        float4 v = {acc[i][0], acc[i][1], acc[i][2], acc[i][3]};
        *(float4*)&g_xm[(size_t)(row0 + r0 + i) * 128 + g * 32 + o0] = v;
    }
}

// ---------------- kernel 8: gate + mix + out-projection (WMMA) ----------------
__global__ __launch_bounds__(256) void k_gateproj(
        const float* __restrict__ gW, const float* __restrict__ gb,
        const float* __restrict__ pW, const float* __restrict__ pb,
        float* __restrict__ out) {
    // sA (xn / mixed, fp16 [r][k] ld 136) reused as sM after gate GEMM.
    __shared__ __align__(32) __half sA[32 * 136];   // 8704 B
    __shared__ __align__(32) __half sB2[64 * 136];  // 17408 B (weights chunk [kk][o])
    __shared__ __align__(32) float  sC[32 * 132];   // 16896 B
    int tile = blockIdx.x;            // 512 tiles of 32 rows
    int row0 = tile * 32;
    int tid = threadIdx.x;            // 256
    int warp = tid >> 5;

    // stage xn -> sA fp16 [r][k]
    for (int i = tid; i < 4096; i += 256) {
        int r = i >> 7, k = i & 127;
        sA[r * 136 + k] = __float2half(g_xn[(size_t)(row0 + r) * 128 + k]);
    }

    // ---- gate GEMM: C = A(32x128) @ gW^T(128x128) ----
    {
        wmma::fragment<wmma::accumulator, 16, 16, 16, float> cf[2];
        wmma::fill_fragment(cf[0], 0.f);
        wmma::fill_fragment(cf[1], 0.f);
        for (int chunk = 0; chunk < 2; chunk++) {
            __syncthreads();
            int c0 = chunk * 64;
            for (int i = tid; i < 8192; i += 256) {
                int o = i >> 6, kk = i & 63;
                sB2[kk * 136 + o] = __float2half(gW[o * 128 + c0 + kk]);
            }
            __syncthreads();
#pragma unroll
            for (int tt = 0; tt < 2; tt++) {
                int t = warp + tt * 8;
                int mi = t & 1, ni = t >> 1;
#pragma unroll
                for (int k0 = 0; k0 < 4; k0++) {
                    wmma::fragment<wmma::matrix_a, 16, 16, 16, __half, wmma::row_major> af;
                    wmma::fragment<wmma::matrix_b, 16, 16, 16, __half, wmma::row_major> bf;
                    wmma::load_matrix_sync(af, &sA[(mi * 16) * 136 + c0 + k0 * 16], 136);
                    wmma::load_matrix_sync(bf, &sB2[(k0 * 16) * 136 + ni * 16], 136);
                    wmma::mma_sync(cf[tt], af, bf, cf[tt]);
                }
            }
        }
#pragma unroll
        for (int tt = 0; tt < 2; tt++) {
            int t = warp + tt * 8;
            int mi = t & 1, ni = t >> 1;
            wmma::store_matrix_sync(&sC[(mi * 16) * 132 + ni * 16], cf[tt], 132, wmma::mem_row_major);
        }
    }
    __syncthreads();

    // ---- gate/mix: sM (=sA) fp16 [r][k] ----
    for (int i = tid; i < 4096; i += 256) {
        int r = i >> 7, o = i & 127;
        size_t gi = (size_t)(row0 + r) * 128 + o;
        float gate = 1.f / (1.f + __expf(-(sC[r * 132 + o] + gb[o])));
        float m = gate * g_xm[gi] + (1.f - gate) * g_xs[gi];
        sA[r * 136 + o] = __float2half(m);
    }

    // ---- proj GEMM: C = sM(32x128) @ pW^T(128x128) ----
    {
        wmma::fragment<wmma::accumulator, 16, 16, 16, float> cf[2];
        wmma::fill_fragment(cf[0], 0.f);
        wmma::fill_fragment(cf[1], 0.f);
        for (int chunk = 0; chunk < 2; chunk++) {
            __syncthreads();
            int c0 = chunk * 64;
            for (int i = tid; i < 8192; i += 256) {
                int o = i >> 6, kk = i & 63;
                sB2[kk * 136 + o] = __float2half(pW[o * 128 + c0 + kk]);
            }
            __syncthreads();
#pragma unroll
            for (int tt = 0; tt < 2; tt++) {
                int t = warp + tt * 8;
                int mi = t & 1, ni = t >> 1;
#pragma unroll
                for (int k0 = 0; k0 < 4; k0++) {
                    wmma::fragment<wmma::matrix_a, 16, 16, 16, __half, wmma::row_major> af;
                    wmma::fragment<wmma::matrix_b, 16, 16, 16, __half, wmma::row_major> bf;
                    wmma::load_matrix_sync(af, &sA[(mi * 16) * 136 + c0 + k0 * 16], 136);
                    wmma::load_matrix_sync(bf, &sB2[(k0 * 16) * 136 + ni * 16], 136);
                    wmma::mma_sync(cf[tt], af, bf, cf[tt]);
                }
            }
        }
#pragma unroll
        for (int tt = 0; tt < 2; tt++) {
            int t = warp + tt * 8;
            int mi = t & 1, ni = t >> 1;
            wmma::store_matrix_sync(&sC[(mi * 16) * 132 + ni * 16], cf[tt], 132, wmma::mem_row_major);
        }
    }
    __syncthreads();

    // transpose-write output (+pb)
    int b = row0 >> 12;
    int l0 = row0 & 4095;
    for (int idx = tid; idx < 4096; idx += 256) {
        int o = idx >> 5, rr = idx & 31;
        out[((size_t)(b * 128 + o)) * 4096 + l0 + rr] = sC[rr * 132 + o] + pb[o];
    }
}

// ---------------- launch ----------------
extern "C" void kernel_launch(void* const* d_in, const int* in_sizes, int n_in,
                              void* d_out, int out_size) {
    const float* x    = (const float*)d_in[0];
    const float* pcw  = (const float*)d_in[1];
    const float* pcb  = (const float*)d_in[2];
    const float* pe   = (const float*)d_in[3];
    const float* lng  = (const float*)d_in[4];
    const float* lnb  = (const float*)d_in[5];
    const float* gW   = (const float*)d_in[6];
    const float* gb   = (const float*)d_in[7];
    const float* pW   = (const float*)d_in[8];
    const float* pb   = (const float*)d_in[9];
    const float* Win  = (const float*)d_in[10];
    const float* Wout = (const float*)d_in[11];
    const float* cw   = (const float*)d_in[12];
    const float* cb   = (const float*)d_in[13];
    const float* xpw  = (const float*)d_in[14];
    const float* dtw  = (const float*)d_in[15];
    const float* dtb  = (const float*)d_in[16];
    const float* alog = (const float*)d_in[17];
    const float* Dk   = (const float*)d_in[18];
    float* out = (float*)d_out;

    k_checkA<<<1, 128>>>(alog);
    k_posln<<<Bq * Hh, 256>>>(x, pcw, pcb, lng, lnb, pe);
    k_win<<<Gg * 256, 256>>>(Win);
    k_convproj<<<Gg * 2 * Bq * 64, 256>>>(cw, cb, xpw, dtw, dtb);
    k_scan<1><<<(32 * NCk) / 2, 128>>>(alog, Dk);
    k_scanfix<<<128, 128>>>();
    k_scan<2><<<(32 * NCk) / 2, 128>>>(alog, Dk);
    k_wout<<<Gg * 256, 128>>>(Wout);
    k_gateproj<<<(Bq * Ll) / 32, 256>>>(gW, gb, pW, pb, out);
}

// round 16
// speedup vs baseline: 1.0594x; 1.0594x over previous
#include <cuda_runtime.h>
#include <cuda_bf16.h>
#include <cuda_fp16.h>
#include <mma.h>
#include <math.h>

using namespace nvcuda;

// ---------------- problem constants ----------------
#define Bq   4
#define Cc   128
#define Hh   64
#define Ww   64
#define Ll   4096          // H*W
#define Gg   4
#define DIi  64
#define DSs  16
#define NCk  64            // number of scan chunks
#define CTk  64            // chunk length  (NCk*CTk == Ll)

typedef unsigned long long ull;

// ---------------- f32x2 helpers ----------------
__device__ __forceinline__ ull pk2(float a, float b) {
    ull r; asm("mov.b64 %0,{%1,%2};" : "=l"(r) : "f"(a), "f"(b)); return r;
}
__device__ __forceinline__ void upk2(ull v, float& a, float& b) {
    asm("mov.b64 {%0,%1},%2;" : "=f"(a), "=f"(b) : "l"(v));
}
__device__ __forceinline__ ull f2fma(ull a, ull b, ull c) {
    ull r; asm("fma.rn.f32x2 %0,%1,%2,%3;" : "=l"(r) : "l"(a), "l"(b), "l"(c)); return r;
}
__device__ __forceinline__ ull f2mul(ull a, ull b) {
    ull r; asm("mul.rn.f32x2 %0,%1,%2;" : "=l"(r) : "l"(a), "l"(b)); return r;
}

// ---------------- scratch ----------------
__device__ float g_xs[Bq * Ll * Cc];
__device__ float g_xn[Bq * Ll * Cc];
__device__ __align__(16) __half g_u2[Gg * Bq * Ll * DIi];     // u fp16
__device__ __align__(16) __half g_z2[Gg * Bq * Ll * DIi];     // z fp16
__device__ __half2 g_du2[Gg * 2 * Bq * Ll * DIi];             // (dt, uc) fp16 pair
__device__ __half2 g_Bm2[Gg * 2 * Bq * Ll * 8];               // B fp16, pairs
__device__ __half2 g_Cm2[Gg * 2 * Bq * Ll * 8];               // C fp16, pairs
__device__ __align__(16) __half g_y2[Gg * 2 * Bq * Ll * DIi]; // y fp16
__device__ float g_xm[Bq * Ll * Cc];
__device__ float g_cq[32 * NCk * DIi];                        // scalar chunk decay q
__device__ __align__(16) float g_carryQ[32 * NCk * DIi * DSs];
__device__ __align__(16) float g_hstart[32 * NCk * DIi * DSs];
__device__ int g_fastflag;

// ---------------- kernel 0: S4D structure check (hoisted) ----------------
__global__ void k_checkA(const float* __restrict__ A_log) {
    int ok = 1;
    for (int i = threadIdx.x; i < Gg * 2 * DIi * DSs; i += 128) {
        int s = i & 15;
        float Av = __expf(A_log[i]);
        if (fabsf(Av - (float)(s + 1)) > 1e-3f * (float)(s + 1)) ok = 0;
    }
    ok = __syncthreads_and(ok);
    if (threadIdx.x == 0) g_fastflag = ok;
}

// ---------------- kernel 1: conv-pos-enc + pos_embed + LayerNorm ----------------
__global__ void k_posln(const float* __restrict__ x, const float* __restrict__ pcw,
                        const float* __restrict__ pcb, const float* __restrict__ lng,
                        const float* __restrict__ lnb, const float* __restrict__ pe) {
    __shared__ float sv[64 * 129];
    __shared__ float sw[128 * 9];
    __shared__ float smu[64], srs[64];
    int b = blockIdx.x >> 6;
    int h = blockIdx.x & 63;
    int tid = threadIdx.x;
    for (int i = tid; i < 128 * 9; i += 256) sw[i] = pcw[i];
    __syncthreads();
    for (int idx = tid; idx < 8192; idx += 256) {
        int c = idx >> 6, w = idx & 63;
        const float* xb = x + ((size_t)(b * Cc + c)) * (Hh * Ww);
        float acc = 0.f;
#pragma unroll
        for (int kh = 0; kh < 3; kh++) {
            int hh = h + kh - 1;
            if (hh < 0 || hh >= Hh) continue;
#pragma unroll
            for (int kw = 0; kw < 3; kw++) {
                int w2 = w + kw - 1;
                if (w2 < 0 || w2 >= Ww) continue;
                acc += xb[hh * Ww + w2] * sw[c * 9 + kh * 3 + kw];
            }
        }
        sv[w * 129 + c] = xb[h * Ww + w] + acc + pcb[c];
    }
    __syncthreads();
    for (int idx = tid; idx < 8192; idx += 256) {
        int l = idx >> 7, c = idx & 127;
        sv[l * 129 + c] += pe[((size_t)(h * 64 + l)) * 128 + c];
    }
    __syncthreads();
    if (tid < 64) {
        float s = 0.f, s2 = 0.f;
        for (int c = 0; c < 128; c++) { float v = sv[tid * 129 + c]; s += v; s2 += v * v; }
        float mu = s * (1.f / 128.f);
        float var = s2 * (1.f / 128.f) - mu * mu;
        smu[tid] = mu;
        srs[tid] = rsqrtf(var + 1e-5f);
    }
    __syncthreads();
    size_t base = ((size_t)b * Ll + h * Ww) * Cc;
    for (int idx = tid; idx < 8192; idx += 256) {
        int l = idx >> 7, c = idx & 127;
        float v = sv[l * 129 + c];
        g_xs[base + idx] = v;
        g_xn[base + idx] = (v - smu[l]) * srs[l] * lng[c] + lnb[c];
    }
}

// ---------------- kernel 2: per-group in-projection; u,z stored fp16 ----------------
__global__ void k_win(const float* __restrict__ Win) {
    int g = blockIdx.x >> 8;
    int tile = blockIdx.x & 255;
    int row0 = tile * 64;
    int tid = threadIdx.x;
    __shared__ float sX[32 * 68];   // [k][r]
    __shared__ float sW[32 * 132];  // [k][o]
    for (int i = tid; i < 2048; i += 256) {
        int r = i >> 5, k = i & 31;
        sX[k * 68 + r] = g_xn[(size_t)(row0 + r) * 128 + g * 32 + k];
    }
    for (int i = tid; i < 4096; i += 256) {
        int o = i >> 5, k = i & 31;
        sW[k * 132 + o] = Win[g * 4096 + i];
    }
    __syncthreads();
    int rg = tid & 15, og = tid >> 4;
    int r0 = rg * 4, o0 = og * 8;
    float acc[4][8];
#pragma unroll
    for (int i = 0; i < 4; i++)
#pragma unroll
        for (int j = 0; j < 8; j++) acc[i][j] = 0.f;
#pragma unroll 4
    for (int k = 0; k < 32; k++) {
        float4 xv = *(const float4*)&sX[k * 68 + r0];
        float4 wa = *(const float4*)&sW[k * 132 + o0];
        float4 wb = *(const float4*)&sW[k * 132 + o0 + 4];
        float xr[4] = {xv.x, xv.y, xv.z, xv.w};
        float wv[8] = {wa.x, wa.y, wa.z, wa.w, wb.x, wb.y, wb.z, wb.w};
#pragma unroll
        for (int i = 0; i < 4; i++)
#pragma unroll
            for (int j = 0; j < 8; j++) acc[i][j] += xr[i] * wv[j];
    }
#pragma unroll
    for (int i = 0; i < 4; i++) {
        size_t row = (size_t)(row0 + r0 + i);
        __half2 h0 = __floats2half2_rn(acc[i][0], acc[i][1]);
        __half2 h1 = __floats2half2_rn(acc[i][2], acc[i][3]);
        __half2 h2v = __floats2half2_rn(acc[i][4], acc[i][5]);
        __half2 h3 = __floats2half2_rn(acc[i][6], acc[i][7]);
        if (og < 8) {
            __half2* p = (__half2*)&g_u2[((size_t)g * (Bq * Ll) + row) * 64 + o0];
            p[0] = h0; p[1] = h1; p[2] = h2v; p[3] = h3;
        } else {
            __half2* p = (__half2*)&g_z2[((size_t)g * (Bq * Ll) + row) * 64 + (o0 - 64)];
            p[0] = h0; p[1] = h1; p[2] = h2v; p[3] = h3;
        }
    }
}

// ---------------- kernel 3: causal dwconv + silu + xproj(WMMA) + dt ----------------
__global__ __launch_bounds__(256) void k_convproj(
        const float* __restrict__ conv_w, const float* __restrict__ conv_b,
        const float* __restrict__ xproj_W, const float* __restrict__ dt_W,
        const float* __restrict__ dt_b) {
    __shared__ __align__(32) float su[64 * 73];        // [di][j<73]
    __shared__ __align__(32) __half suc_h[64 * 72];    // [di][tl<72]  == A col-major ld 72
    __half* sxw_h = (__half*)su;                       // [k=di][o<40] row-major ld 40
    float*  sdbl  = su + 1280;                         // [tl][o<48]   ld 48

    int bi = blockIdx.x;            // 2048 blocks
    int tile = bi & 63;
    int b = (bi >> 6) & 3;
    int dir = (bi >> 8) & 1;
    int g = bi >> 9;
    int tid = threadIdx.x;
    int gd = g * 2 + dir;
    int t0 = tile * 64;

    // stage u (fp16 -> fp32) via half2, rows t0-3 .. t0+66
    const __half* ub = g_u2 + ((size_t)g * Bq + b) * Ll * 64;
    for (int i = tid; i < 70 * 32; i += 256) {
        int j = i >> 5;
        int di2 = (i & 31) * 2;
        int t = t0 - 3 + j;
        float lo = 0.f, hi = 0.f;
        if (t >= 0 && t < Ll) {
            float2 v = __half22float2(*(const __half2*)&ub[(size_t)t * 64 + di2]);
            lo = v.x; hi = v.y;
        }
        su[di2 * 73 + j] = lo;
        su[(di2 + 1) * 73 + j] = hi;
    }
    __syncthreads();

    // conv + silu -> suc_h (half), sliding window
    {
        int di = tid & 63;
        int tlg = tid >> 6;
        int tl0 = tlg * 16;
        float w0 = conv_w[gd * 256 + di * 4 + 0];
        float w1 = conv_w[gd * 256 + di * 4 + 1];
        float w2 = conv_w[gd * 256 + di * 4 + 2];
        float w3 = conv_w[gd * 256 + di * 4 + 3];
        float cb = conv_b[gd * 64 + di];
        const float* sud = &su[di * 73];
        if (dir == 0) {
            float x0 = sud[tl0 + 0], x1 = sud[tl0 + 1], x2 = sud[tl0 + 2];
#pragma unroll
            for (int m = 0; m < 16; m++) {
                float x3 = sud[tl0 + m + 3];
                float a = w0 * x0 + w1 * x1 + w2 * x2 + w3 * x3 + cb;
                suc_h[di * 72 + tl0 + m] = __float2half(a / (1.f + __expf(-a)));
                x0 = x1; x1 = x2; x2 = x3;
            }
        } else {
            float x0 = sud[tl0 + 3], x1 = sud[tl0 + 4], x2 = sud[tl0 + 5];
#pragma unroll
            for (int m = 0; m < 16; m++) {
                float x3 = sud[tl0 + m + 6];
                float a = w3 * x0 + w2 * x1 + w1 * x2 + w0 * x3 + cb;
                suc_h[di * 72 + tl0 + m] = __float2half(a / (1.f + __expf(-a)));
                x0 = x1; x1 = x2; x2 = x3;
            }
        }
    }
    __syncthreads();

    // stage xproj weights (half), [k][o] ld 40; zero pads o=34..39
    for (int i = tid; i < 2176; i += 256) {
        int o = i >> 6, di = i & 63;
        sxw_h[di * 40 + o] = __float2half(xproj_W[gd * 2176 + i]);
    }
    for (int i = tid; i < 384; i += 256) {
        int k = i / 6, o = 34 + (i % 6);
        sxw_h[k * 40 + o] = __float2half(0.f);
    }
    __syncthreads();

    // WMMA GEMM: out[tl 64][o 48] = A(suc_h col-major) @ B(sxw_h row-major)
    {
        int warp = tid >> 5;
        for (int t = warp; t < 12; t += 8) {
            int mi = t & 3;
            int ni = t >> 2;
            wmma::fragment<wmma::accumulator, 16, 16, 16, float> cf;
            wmma::fill_fragment(cf, 0.f);
#pragma unroll
            for (int k0 = 0; k0 < 4; k0++) {
                wmma::fragment<wmma::matrix_a, 16, 16, 16, __half, wmma::col_major> af;
                wmma::fragment<wmma::matrix_b, 16, 16, 16, __half, wmma::row_major> bf;
                wmma::load_matrix_sync(af, &suc_h[(k0 * 16) * 72 + mi * 16], 72);
                wmma::load_matrix_sync(bf, &sxw_h[(k0 * 16) * 40 + ni * 16], 40);
                wmma::mma_sync(cf, af, bf, cf);
            }
            wmma::store_matrix_sync(&sdbl[(mi * 16) * 48 + ni * 16], cf, 48, wmma::mem_row_major);
        }
    }
    __syncthreads();

    // dt phase: write packed (dt, uc) fp16 pair
    __half2* dug = g_du2 + ((size_t)gd * Bq + b) * Ll * 64;
    {
        int di = tid & 63;
        int tlg = tid >> 6;
        float dw0 = dt_W[gd * 128 + di * 2 + 0];
        float dw1 = dt_W[gd * 128 + di * 2 + 1];
        float db  = dt_b[gd * 64 + di];
#pragma unroll 4
        for (int m = 0; m < 16; m++) {
            int tl = tlg * 16 + m;
            float r = sdbl[tl * 48 + 0] * dw0 + sdbl[tl * 48 + 1] * dw1 + db;
            float sp = (r > 15.f) ? r : log1pf(__expf(r));
            __half2 v;
            v.x = __float2half(sp);
            v.y = suc_h[di * 72 + tl];
            dug[(size_t)(t0 + tl) * 64 + di] = v;
        }
    }
    __half2* Bmg = g_Bm2 + ((size_t)gd * Bq + b) * Ll * 8;
    __half2* Cmg = g_Cm2 + ((size_t)gd * Bq + b) * Ll * 8;
    for (int i = tid; i < 512; i += 256) {
        int tl = i >> 3, dsp = i & 7;
        Bmg[(size_t)(t0 + tl) * 8 + dsp] =
            __floats2half2_rn(sdbl[tl * 48 + 2 + dsp * 2], sdbl[tl * 48 + 3 + dsp * 2]);
        Cmg[(size_t)(t0 + tl) * 8 + dsp] =
            __floats2half2_rn(sdbl[tl * 48 + 18 + dsp * 2], sdbl[tl * 48 + 19 + dsp * 2]);
    }
}

// ---------------- kernels 4/6: chunked selective scan (fp16 streams, hoisted A-check) ----------------
template <int PASS>
__global__ __launch_bounds__(128, 8) void k_scan(const float* __restrict__ A_log,
                                                 const float* __restrict__ Dskip) {
    __shared__ __align__(16) float sB[2][CTk * 16];
    __shared__ __align__(16) float sC_[2][CTk * 16];
    int tid = threadIdx.x;
    int unit = tid >> 6;
    int di = tid & 63;
    int ug = blockIdx.x * 2 + unit;
    int seq = ug >> 6;
    int c = ug & 63;
    int b = seq & 3;
    int dir = (seq >> 2) & 1;
    int g = seq >> 3;
    int gd = g * 2 + dir;
    size_t base_td = ((size_t)gd * Bq + b) * Ll * 64;
    size_t base_s2 = ((size_t)gd * Bq + b) * Ll * 8;
    size_t base_z  = ((size_t)g * Bq + b) * Ll * 64;
    int sigma0 = c * CTk;
    int tstart = dir ? (Ll - 1 - sigma0) : sigma0;
    int tstep  = dir ? -1 : 1;
    const __half2* Bm2 = g_Bm2 + base_s2;
    const __half2* Cm2 = g_Cm2 + base_s2;
    for (int i = di; i < CTk * 8; i += 64) {
        int sl = i >> 3, dsp = i & 7;
        int t = tstart + tstep * sl;
        *(float2*)&sB[unit][sl * 16 + dsp * 2] = __half22float2(Bm2[(size_t)t * 8 + dsp]);
        if (PASS == 2)
            *(float2*)&sC_[unit][sl * 16 + dsp * 2] = __half22float2(Cm2[(size_t)t * 8 + dsp]);
    }
    int fast = g_fastflag;
    float Dv = (PASS == 2) ? Dskip[gd * 64 + di] : 0.f;
    size_t coff = (((size_t)seq * NCk + c) * 64 + di) * 16;
    __syncthreads();

    int pstep = tstep * 64;
    const __half2* dup = g_du2 + base_td + (size_t)tstart * 64 + di;
    const __half*  zp  = g_z2  + base_z  + (size_t)tstart * 64 + di;
    __half*        yp  = g_y2  + base_td + (size_t)tstart * 64 + di;

    if (fast) {
        ull h2[8];
        if (PASS == 1) {
#pragma unroll
            for (int j = 0; j < 8; j++) h2[j] = 0ull;
        } else {
            const ull* hp = (const ull*)&g_hstart[coff];
#pragma unroll
            for (int j = 0; j < 8; j++) h2[j] = hp[j];
        }
        float sumdt = 0.f;
        float2 cur = __half22float2(__ldg(dup));
        float zcur = (PASS == 2) ? __half2float(__ldg(zp)) : 0.f;
        for (int sl = 0; sl < CTk; sl++) {
            float2 nxt = cur;
            float znxt = zcur;
            if (sl < CTk - 1) {
                dup += pstep;
                nxt = __half22float2(__ldg(dup));
                if (PASS == 2) { zp += pstep; znxt = __half2float(__ldg(zp)); }
            }
            float dtv = cur.x, ucv = cur.y;
            float dtu = dtv * ucv;
            float p = __expf(-dtv);
            float p2 = p * p;
            float p4 = p2 * p2;
            float p8 = p4 * p4;
            ull q2 = pk2(p2, p2);
            ull q4 = pk2(p4, p4);
            ull q8 = pk2(p8, p8);
            ull d0 = pk2(p, p2);
            ull d1 = f2mul(d0, q2);
            ull d2 = f2mul(d0, q4);
            ull d3 = f2mul(d1, q4);
            ull d4 = f2mul(d0, q8);
            ull d5 = f2mul(d1, q8);
            ull d6 = f2mul(d2, q8);
            ull d7 = f2mul(d3, q8);
            ull du2 = pk2(dtu, dtu);
            if (PASS == 1) sumdt += dtv;
            const ull* bp = (const ull*)&sB[unit][sl * 16];
            h2[0] = f2fma(d0, h2[0], f2mul(du2, bp[0]));
            h2[1] = f2fma(d1, h2[1], f2mul(du2, bp[1]));
            h2[2] = f2fma(d2, h2[2], f2mul(du2, bp[2]));
            h2[3] = f2fma(d3, h2[3], f2mul(du2, bp[3]));
            h2[4] = f2fma(d4, h2[4], f2mul(du2, bp[4]));
            h2[5] = f2fma(d5, h2[5], f2mul(du2, bp[5]));
            h2[6] = f2fma(d6, h2[6], f2mul(du2, bp[6]));
            h2[7] = f2fma(d7, h2[7], f2mul(du2, bp[7]));
            if (PASS == 2) {
                const ull* cp = (const ull*)&sC_[unit][sl * 16];
                ull a0 = f2mul(h2[0], cp[0]);
                ull a1 = f2mul(h2[4], cp[4]);
                a0 = f2fma(h2[1], cp[1], a0);
                a1 = f2fma(h2[5], cp[5], a1);
                a0 = f2fma(h2[2], cp[2], a0);
                a1 = f2fma(h2[6], cp[6], a1);
                a0 = f2fma(h2[3], cp[3], a0);
                a1 = f2fma(h2[7], cp[7], a1);
                float x0, x1, x2, x3;
                upk2(a0, x0, x1);
                upk2(a1, x2, x3);
                float y = (x0 + x2) + (x1 + x3) + ucv * Dv;
                y *= zcur / (1.f + __expf(-zcur));
                *yp = __float2half(y);
                yp += pstep;
            }
            cur = nxt;
            zcur = znxt;
        }
        if (PASS == 1) {
            g_cq[((size_t)seq * NCk + c) * 64 + di] = __expf(-sumdt);
            ull* cQ = (ull*)&g_carryQ[coff];
#pragma unroll
            for (int j = 0; j < 8; j++) cQ[j] = h2[j];
        }
    } else {
        float Av[16];
#pragma unroll
        for (int s = 0; s < 16; s++) Av[s] = -__expf(A_log[(gd * 64 + di) * 16 + s]);
        float h[16];
        float sumdt = 0.f;
        if (PASS == 1) {
#pragma unroll
            for (int s = 0; s < 16; s++) h[s] = 0.f;
        } else {
#pragma unroll
            for (int s = 0; s < 16; s++) h[s] = g_hstart[coff + s];
        }
        for (int sl = 0; sl < CTk; sl++) {
            float2 duv = __half22float2(dup[(size_t)(tstep * sl) * 64]);
            float dtv = duv.x, ucv = duv.y;
            float dtu = dtv * ucv;
            float acc = 0.f;
            if (PASS == 1) sumdt += dtv;
#pragma unroll
            for (int s = 0; s < 16; s++) {
                float dA = __expf(dtv * Av[s]);
                h[s] = dA * h[s] + dtu * sB[unit][sl * 16 + s];
                if (PASS == 2) acc += h[s] * sC_[unit][sl * 16 + s];
            }
            if (PASS == 2) {
                float zv = __half2float(zp[(size_t)(tstep * sl) * 64]);
                float y = acc + ucv * Dv;
                y *= zv / (1.f + __expf(-zv));
                yp[(size_t)(tstep * sl) * 64] = __float2half(y);
            }
        }
        if (PASS == 1) {
            g_cq[((size_t)seq * NCk + c) * 64 + di] = __expf(-sumdt);
#pragma unroll
            for (int s = 0; s < 16; s++) g_carryQ[coff + s] = h[s];
        }
    }
}

// ---------------- kernel 5: compose chunk carries (q-power reconstruction) ----------------
__global__ void k_scanfix() {
    int idx = blockIdx.x * 128 + threadIdx.x;
    int seq = idx >> 9;
    int e2 = idx & 511;
    int di = e2 >> 3;
    int j  = e2 & 7;
    ull h = 0ull;
    const ull* Q = (const ull*)g_carryQ;
    ull* H = (ull*)g_hstart;
#pragma unroll 8
    for (int c = 0; c < NCk; c++) {
        size_t off = ((size_t)seq * NCk + c) * 512 + e2;
        float q = g_cq[((size_t)seq * NCk + c) * 64 + di];
        float q2 = q * q;
        float q4 = q2 * q2;
        float q8 = q4 * q4;
        float qp = ((j & 1) ? q2 : 1.f) * ((j & 2) ? q4 : 1.f) * ((j & 4) ? q8 : 1.f);
        ull P = pk2(q * qp, q2 * qp);
        H[off] = h;
        h = f2fma(P, h, Q[off]);
    }
}

// ---------------- kernel 7: (yf+yb) @ Wout^T -> x_mamba, register tiled ----------------
__global__ void k_wout(const float* __restrict__ Wout) {
    int g = blockIdx.x >> 8;
    int tile = blockIdx.x & 255;
    int row0 = tile * 64;
    int tid = threadIdx.x;    // 128 threads
    __shared__ float sY[64 * 68];   // [k][r]
    __shared__ float sW[64 * 36];   // [k][o]
    size_t basef = ((size_t)(g * 2 + 0) * Bq) * Ll * 64;
    size_t baseb = ((size_t)(g * 2 + 1) * Bq) * Ll * 64;
    for (int i = tid; i < 4096; i += 128) {
        int r = i >> 6, k = i & 63;
        size_t ro = (size_t)(row0 + r) * 64 + k;
        sY[k * 68 + r] = __half2float(g_y2[basef + ro]) + __half2float(g_y2[baseb + ro]);
    }
    for (int i = tid; i < 2048; i += 128) {
        int o = i >> 6, k = i & 63;
        sW[k * 36 + o] = Wout[g * 2048 + i];
    }
    __syncthreads();
    int rg = tid & 15, og = tid >> 4;
    int r0 = rg * 4, o0 = og * 4;
    float acc[4][4];
#pragma unroll
    for (int i = 0; i < 4; i++)
#pragma unroll
        for (int j = 0; j < 4; j++) acc[i][j] = 0.f;
#pragma unroll 4
    for (int k = 0; k < 64; k++) {
        float4 yv = *(const float4*)&sY[k * 68 + r0];
        float4 wv = *(const float4*)&sW[k * 36 + o0];
        float yr[4] = {yv.x, yv.y, yv.z, yv.w};
        float wr[4] = {wv.x, wv.y, wv.z, wv.w};
#pragma unroll
        for (int i = 0; i < 4; i++)
#pragma unroll
            for (int j = 0; j < 4; j++) acc[i][j] += yr[i] * wr[j];
    }
#pragma unroll
    for (int i = 0; i < 4; i++) {
        float4 v = {acc[i][0], acc[i][1], acc[i][2], acc[i][3]};
        *(float4*)&g_xm[(size_t)(row0 + r0 + i) * 128 + g * 32 + o0] = v;
    }
}

// ---------------- kernel 8: gate + mix + out-projection, register tiled (fp32) ----------------
__global__ void k_gateproj(const float* __restrict__ gW, const float* __restrict__ gb,
                           const float* __restrict__ pW, const float* __restrict__ pb,
                           float* __restrict__ out) {
    int tile = blockIdx.x;            // 512 tiles of 32 rows
    int row0 = tile * 32;
    int tid = threadIdx.x;            // 256
    __shared__ float sIn[128 * 36];   // [k][r]  (reused as sOut [o][r pad 33])
    __shared__ float sWt[32 * 132];   // [kk][o]
    __shared__ float sM [128 * 36];   // [k][r]
    int rg = tid & 7, og = tid >> 3;
    int r0 = rg * 4, o0 = og * 4;
    float acc[4][4];
#pragma unroll
    for (int i = 0; i < 4; i++)
#pragma unroll
        for (int j = 0; j < 4; j++) acc[i][j] = 0.f;

    for (int i = tid; i < 4096; i += 256) {
        int r = i >> 7, k = i & 127;
        sIn[k * 36 + r] = g_xn[(size_t)(row0 + r) * 128 + k];
    }
    for (int ko = 0; ko < 4; ko++) {
        __syncthreads();
        for (int i = tid; i < 4096; i += 256) {
            int o = i >> 5, kk = i & 31;
            sWt[kk * 132 + o] = gW[o * 128 + ko * 32 + kk];
        }
        __syncthreads();
#pragma unroll 4
        for (int kk = 0; kk < 32; kk++) {
            int k = ko * 32 + kk;
            float4 xv = *(const float4*)&sIn[k * 36 + r0];
            float4 wv = *(const float4*)&sWt[kk * 132 + o0];
            float xr[4] = {xv.x, xv.y, xv.z, xv.w};
            float wr[4] = {wv.x, wv.y, wv.z, wv.w};
#pragma unroll
            for (int i = 0; i < 4; i++)
#pragma unroll
                for (int j = 0; j < 4; j++) acc[i][j] += xr[i] * wr[j];
        }
    }
#pragma unroll
    for (int i = 0; i < 4; i++) {
        size_t gi = (size_t)(row0 + r0 + i) * 128 + o0;
        float4 xmv = *(const float4*)&g_xm[gi];
        float4 xsv = *(const float4*)&g_xs[gi];
        float xm[4] = {xmv.x, xmv.y, xmv.z, xmv.w};
        float xs[4] = {xsv.x, xsv.y, xsv.z, xsv.w};
#pragma unroll
        for (int j = 0; j < 4; j++) {
            float gate = 1.f / (1.f + __expf(-(acc[i][j] + gb[o0 + j])));
            sM[(o0 + j) * 36 + r0 + i] = gate * xm[j] + (1.f - gate) * xs[j];
            acc[i][j] = 0.f;
        }
    }
    for (int ko = 0; ko < 4; ko++) {
        __syncthreads();
        for (int i = tid; i < 4096; i += 256) {
            int o = i >> 5, kk = i & 31;
            sWt[kk * 132 + o] = pW[o * 128 + ko * 32 + kk];
        }
        __syncthreads();
#pragma unroll 4
        for (int kk = 0; kk < 32; kk++) {
            int k = ko * 32 + kk;
            float4 xv = *(const float4*)&sM[k * 36 + r0];
            float4 wv = *(const float4*)&sWt[kk * 132 + o0];
            float xr[4] = {xv.x, xv.y, xv.z, xv.w};
            float wr[4] = {wv.x, wv.y, wv.z, wv.w};
#pragma unroll
            for (int i = 0; i < 4; i++)
#pragma unroll
                for (int j = 0; j < 4; j++) acc[i][j] += xr[i] * wr[j];
        }
    }
    __syncthreads();
    float* sOut = sIn;   // [o][r pad 33]
#pragma unroll
    for (int i = 0; i < 4; i++)
#pragma unroll
        for (int j = 0; j < 4; j++)
            sOut[(o0 + j) * 33 + r0 + i] = acc[i][j] + pb[o0 + j];
    __syncthreads();
    int b = row0 >> 12;
    int l0 = row0 & 4095;
    for (int idx = tid; idx < 4096; idx += 256) {
        int o = idx >> 5, rr = idx & 31;
        out[((size_t)(b * 128 + o)) * 4096 + l0 + rr] = sOut[o * 33 + rr];
    }
}

// ---------------- launch ----------------
extern "C" void kernel_launch(void* const* d_in, const int* in_sizes, int n_in,
                              void* d_out, int out_size) {
    const float* x    = (const float*)d_in[0];
    const float* pcw  = (const float*)d_in[1];
    const float* pcb  = (const float*)d_in[2];
    const float* pe   = (const float*)d_in[3];
    const float* lng  = (const float*)d_in[4];
    const float* lnb  = (const float*)d_in[5];
    const float* gW   = (const float*)d_in[6];
    const float* gb   = (const float*)d_in[7];
    const float* pW   = (const float*)d_in[8];
    const float* pb   = (const float*)d_in[9];
    const float* Win  = (const float*)d_in[10];
    const float* Wout = (const float*)d_in[11];
    const float* cw   = (const float*)d_in[12];
    const float* cb   = (const float*)d_in[13];
    const float* xpw  = (const float*)d_in[14];
    const float* dtw  = (const float*)d_in[15];
    const float* dtb  = (const float*)d_in[16];
    const float* alog = (const float*)d_in[17];
    const float* Dk   = (const float*)d_in[18];
    float* out = (float*)d_out;

    k_checkA<<<1, 128>>>(alog);
    k_posln<<<Bq * Hh, 256>>>(x, pcw, pcb, lng, lnb, pe);
    k_win<<<Gg * 256, 256>>>(Win);
    k_convproj<<<Gg * 2 * Bq * 64, 256>>>(cw, cb, xpw, dtw, dtb);
    k_scan<1><<<(32 * NCk) / 2, 128>>>(alog, Dk);
    k_scanfix<<<128, 128>>>();
    k_scan<2><<<(32 * NCk) / 2, 128>>>(alog, Dk);
    k_wout<<<Gg * 256, 128>>>(Wout);
    k_gateproj<<<(Bq * Ll) / 32, 256>>>(gW, gb, pW, pb, out);
}